// round 15
// baseline (speedup 1.0000x reference)
#include <cuda_runtime.h>
#include <cuda_fp16.h>
#include <math.h>
#include <cstdint>

// ContactMapHead via single-pass fp16 HMMA GEMMs (tcgen05 rejected by sm_103
// PTX target). fp16 products are exact in the fp32 accumulator.
//   h      = relu(hs @ W^T + b)        hs:[8192,1024] W:[256,1024]
//   scores = (h @ h^T) * s + c         per batch of 4, S=2048
// R14: scores uses 128x128 fully-resident tiles (256 rows x 528B = 132KB smem,
// 512 threads / 16 warps, zero-barrier mainloop) -> 33% less load traffic and
// half the CTAs vs R13. Proj/convert_w = exact validated R12 code.

#define B_    4
#define S_    2048
#define D_    1024
#define P_    256
#define MROWS 8192

#define BK    32

// ---- proj smem layout: B 4-stage (ROWB=80) + A 2-slot fp16 staging ----
#define PROJ_ROWB   80
#define PROJ_BSTAGE (128 * PROJ_ROWB)         // 10240
#define PROJ_AOFF   (4 * PROJ_BSTAGE)         // 40960
#define PROJ_ASLOT  (64 * PROJ_ROWB)          // 5120
#define PROJ_SMEM   (PROJ_AOFF + 2 * PROJ_ASLOT)   // 51200

// ---- scores smem: fully-resident 128x256 A + 128x256 B, 528B padded rows ----
#define SC_ROWB   528                          // 512 data + 16 pad
#define SC_BOFF   (128 * SC_ROWB)              // 67584 (A region size)
#define SC_SMEM   (256 * SC_ROWB)              // 135168 (epi 128*132*4=67584 fits)

// ---------------- scratch ----------------
__device__ unsigned short g_w16[(size_t)P_ * D_];
__device__ unsigned short g_h16[(size_t)MROWS * P_];

// ---------------- asm helpers ----------------
__device__ __forceinline__ uint32_t smem_u32(const void* p) {
    uint32_t a;
    asm("{ .reg .u64 t; cvta.to.shared.u64 t, %1; cvt.u32.u64 %0, t; }" : "=r"(a) : "l"(p));
    return a;
}
__device__ __forceinline__ void cpa16(uint32_t s, const void* g) {
    asm volatile("cp.async.cg.shared.global [%0], [%1], 16;" :: "r"(s), "l"(g));
}
#define CP_COMMIT() asm volatile("cp.async.commit_group;" ::: "memory")
#define CP_WAIT2()  asm volatile("cp.async.wait_group 2;" ::: "memory")
#define CP_WAIT0()  asm volatile("cp.async.wait_group 0;" ::: "memory")

#define LDMX4(r, addr) \
    asm volatile("ldmatrix.sync.aligned.m8n8.x4.shared.b16 {%0,%1,%2,%3}, [%4];" \
        : "=r"((r)[0]), "=r"((r)[1]), "=r"((r)[2]), "=r"((r)[3]) : "r"(addr))

#define MMA16816(d, a, b0, b1) \
    asm volatile("mma.sync.aligned.m16n8k16.row.col.f32.f16.f16.f32 " \
        "{%0,%1,%2,%3},{%4,%5,%6,%7},{%8,%9},{%0,%1,%2,%3};" \
        : "+f"((d)[0]), "+f"((d)[1]), "+f"((d)[2]), "+f"((d)[3]) \
        : "r"((a)[0]), "r"((a)[1]), "r"((a)[2]), "r"((a)[3]), "r"(b0), "r"(b1))

#define STS128(addr, v) \
    asm volatile("st.shared.v4.b32 [%0], {%1,%2,%3,%4};" \
        :: "r"(addr), "r"((v).x), "r"((v).y), "r"((v).z), "r"((v).w))

// ---------------- fp32 -> fp16 convert for W only (0.5 MB) ----------------
__global__ __launch_bounds__(256) void convert_w_kernel(
    const float* __restrict__ w, unsigned short* __restrict__ w16)
{
    int i = blockIdx.x * 256 + threadIdx.x;           // (P_*D_)/4 elems
    float4 v = ((const float4*)w)[i];
    __half2 lo = __floats2half2_rn(v.x, v.y);
    __half2 hi = __floats2half2_rn(v.z, v.w);
    uint2 o;
    o.x = *(uint32_t*)&lo;
    o.y = *(uint32_t*)&hi;
    ((uint2*)w16)[i] = o;
}

// ---------------- proj: h = relu(hs@W^T + b) -> h fp16, fused convert -------
// (exact R8/R12 code)
__global__ __launch_bounds__(256) void proj_gemm_kernel(
    const float* __restrict__ hs, const float* __restrict__ bias)
{
    extern __shared__ char smem[];
    uint32_t sbase = smem_u32(smem);
    const int tid = threadIdx.x, lane = tid & 31, w = tid >> 5;
    const int wm = w & 1, wn = w >> 1;
    const int row0 = blockIdx.y * 64, col0 = blockIdx.x * 128;
    const int NC = D_ / BK;   // 32

    const float* aptr = hs + (size_t)(row0 + (tid >> 2)) * D_ + (tid & 3) * 8;
    const uint32_t asts = sbase + PROJ_AOFF + (tid >> 2) * PROJ_ROWB + (tid & 3) * 16;

#pragma unroll
    for (int i = 0; i < 3; i++) {
        uint32_t sB = sbase + i * PROJ_BSTAGE;
#pragma unroll
        for (int q = 0; q < 2; q++) {
            int ch = tid + q * 256;
            int r = ch >> 2, c16 = ch & 3;
            cpa16(sB + r * PROJ_ROWB + c16 * 16,
                  g_w16 + (size_t)(col0 + r) * D_ + i * BK + c16 * 8);
        }
        CP_COMMIT();
    }
    float4 ax = ((const float4*)aptr)[0];
    float4 ay = ((const float4*)aptr)[1];

    float acc[2][4][4] = {};
    const uint32_t aoffm = (wm * 32 + (lane & 15)) * PROJ_ROWB + (lane >> 4) * 16;
    const uint32_t boff  = (wn * 32 + (lane & 15)) * PROJ_ROWB + (lane >> 4) * 16;

    for (int c = 0; c < NC; c++) {
        float4 nx, ny;
        if (c + 1 < NC) {
            const float4* p = (const float4*)(aptr + (c + 1) * BK);
            nx = p[0]; ny = p[1];
        }
        __syncthreads();
        {
            __half2 h0 = __floats2half2_rn(ax.x, ax.y);
            __half2 h1 = __floats2half2_rn(ax.z, ax.w);
            __half2 h2 = __floats2half2_rn(ay.x, ay.y);
            __half2 h3 = __floats2half2_rn(ay.z, ay.w);
            uint4 v = { *(uint32_t*)&h0, *(uint32_t*)&h1,
                        *(uint32_t*)&h2, *(uint32_t*)&h3 };
            STS128(asts + (c & 1) * PROJ_ASLOT, v);
        }
        CP_WAIT2();
        __syncthreads();
        if (c + 3 < NC) {
            uint32_t sB = sbase + ((c + 3) & 3) * PROJ_BSTAGE;
#pragma unroll
            for (int q = 0; q < 2; q++) {
                int ch = tid + q * 256;
                int r = ch >> 2, c16 = ch & 3;
                cpa16(sB + r * PROJ_ROWB + c16 * 16,
                      g_w16 + (size_t)(col0 + r) * D_ + (c + 3) * BK + c16 * 8);
            }
        }
        CP_COMMIT();

        uint32_t sA = sbase + PROJ_AOFF + (c & 1) * PROJ_ASLOT;
        uint32_t sB = sbase + (c & 3) * PROJ_BSTAGE;
#pragma unroll
        for (int k16 = 0; k16 < 2; k16++) {
            uint32_t a[2][4], b[2][4];
#pragma unroll
            for (int mt = 0; mt < 2; mt++)
                LDMX4(a[mt], sA + aoffm + mt * 16 * PROJ_ROWB + k16 * 32);
#pragma unroll
            for (int np = 0; np < 2; np++)
                LDMX4(b[np], sB + boff + np * 16 * PROJ_ROWB + k16 * 32);
#pragma unroll
            for (int mt = 0; mt < 2; mt++)
#pragma unroll
                for (int nt = 0; nt < 4; nt++)
                    MMA16816(acc[mt][nt], a[mt], b[nt >> 1][nt & 1], b[nt >> 1][(nt & 1) + 2]);
        }
        ax = nx; ay = ny;
    }

    uint32_t* hh = (uint32_t*)g_h16;
#pragma unroll
    for (int nt = 0; nt < 4; nt++) {
        int col = col0 + wn * 32 + nt * 8 + (lane & 3) * 2;
        float b0 = bias[col], b1 = bias[col + 1];
#pragma unroll
        for (int mt = 0; mt < 2; mt++) {
            int r0 = row0 + wm * 32 + mt * 16 + (lane >> 2);
#pragma unroll
            for (int hh2 = 0; hh2 < 2; hh2++) {
                int r = r0 + hh2 * 8;
                float v0 = fmaxf(acc[mt][nt][hh2 * 2 + 0] + b0, 0.f);
                float v1 = fmaxf(acc[mt][nt][hh2 * 2 + 1] + b1, 0.f);
                __half2 p = __floats2half2_rn(v0, v1);
                hh[((size_t)r * P_ + col) >> 1] = *(uint32_t*)&p;
            }
        }
    }
}

// ---------------- scores: 128x128 fully-resident tiles, 512 thr, tri+mirror -
// Per batch: 136 triangular tile pairs (bi >= bj). Diagonal tiles (bi==bj)
// compute the full 128x128 block and write direct only; bi>bj also mirrors.
__global__ __launch_bounds__(512) void scores_gemm_kernel(
    const float* __restrict__ clf_w, const float* __restrict__ clf_b,
    float* __restrict__ out)
{
    extern __shared__ char smem[];
    uint32_t sbase = smem_u32(smem);
    const int tid = threadIdx.x, lane = tid & 31, w = tid >> 5;   // w: 0..15
    const int wm = w & 3, wn = w >> 2;                            // 4x4 warp grid

    // triangular decode over 136 pairs
    const int idx = blockIdx.x;
    int bi = (int)((sqrtf(8.f * (float)idx + 1.f) - 1.f) * 0.5f);
    while ((bi + 1) * (bi + 2) / 2 <= idx) bi++;
    while (bi * (bi + 1) / 2 > idx)       bi--;
    const int bj = idx - bi * (bi + 1) / 2;
    const int rows0 = bi * 128, cols0 = bj * 128;
    const bool diag = (bi == bj);

    const unsigned short* hb = g_h16 + (size_t)blockIdx.z * S_ * P_;
    float* outb = out + (size_t)blockIdx.z * S_ * S_;

    // ---- one-shot load: A rows (128, rows0) then B rows (128, cols0) ----
    // 256 rows x 32 chunks(16B) = 8192 chunks / 512 threads = 16 each.
#pragma unroll
    for (int q = 0; q < 16; q++) {
        int ch = tid + q * 512;
        int r = ch >> 5, c16 = ch & 31;
        uint32_t saddr;
        const unsigned short* gaddr;
        if (r < 128) {
            saddr = sbase + r * SC_ROWB + c16 * 16;
            gaddr = hb + (size_t)(rows0 + r) * P_ + c16 * 8;
        } else {
            saddr = sbase + SC_BOFF + (r - 128) * SC_ROWB + c16 * 16;
            gaddr = hb + (size_t)(cols0 + (r - 128)) * P_ + c16 * 8;
        }
        cpa16(saddr, gaddr);
    }
    CP_COMMIT();
    CP_WAIT0();
    __syncthreads();

    // ---- zero-barrier mainloop: 16 k16 steps, warp tile 32x32 ----
    float acc[2][4][4] = {};
    const uint32_t aoffm = (wm * 32 + (lane & 15)) * SC_ROWB + (lane >> 4) * 16;
    const uint32_t boff  = SC_BOFF + (wn * 32 + (lane & 15)) * SC_ROWB + (lane >> 4) * 16;

#pragma unroll
    for (int k16 = 0; k16 < 16; k16++) {
        uint32_t a[2][4], b[2][4];
#pragma unroll
        for (int mt = 0; mt < 2; mt++)
            LDMX4(a[mt], sbase + aoffm + mt * 16 * SC_ROWB + k16 * 32);
#pragma unroll
        for (int np = 0; np < 2; np++)
            LDMX4(b[np], sbase + boff + np * 16 * SC_ROWB + k16 * 32);
#pragma unroll
        for (int mt = 0; mt < 2; mt++)
#pragma unroll
            for (int nt = 0; nt < 4; nt++)
                MMA16816(acc[mt][nt], a[mt], b[nt >> 1][nt & 1], b[nt >> 1][(nt & 1) + 2]);
    }
    __syncthreads();   // all warps done reading operands before epilogue reuse

    const float sw = clf_w[0], cb = clf_b[0];
    float* sep = (float*)smem;   // [128][132] f32 = 67584 (fits in A region)

#pragma unroll
    for (int mt = 0; mt < 2; mt++)
#pragma unroll
        for (int nt = 0; nt < 4; nt++) {
            int lr = wm * 32 + mt * 16 + (lane >> 2);
            int lc = wn * 32 + nt * 8 + (lane & 3) * 2;
            sep[lr * 132 + lc]           = acc[mt][nt][0];
            sep[lr * 132 + lc + 1]       = acc[mt][nt][1];
            sep[(lr + 8) * 132 + lc]     = acc[mt][nt][2];
            sep[(lr + 8) * 132 + lc + 1] = acc[mt][nt][3];
        }
    __syncthreads();

    // direct block: 128 rows x 128 cols (coalesced float4 per row)
#pragma unroll
    for (int pass = 0; pass < 8; pass++) {
        int r = pass * 16 + w;
        float4 v = *(const float4*)(sep + r * 132 + lane * 4);
        v.x = fmaf(v.x, sw, cb); v.y = fmaf(v.y, sw, cb);
        v.z = fmaf(v.z, sw, cb); v.w = fmaf(v.w, sw, cb);
        *(float4*)&outb[(size_t)(rows0 + r) * S_ + cols0 + lane * 4] = v;
    }
    // mirrored block: 128 rows (cols0+c) x 128 cols (rows0..)
    if (!diag) {
#pragma unroll
        for (int pass = 0; pass < 8; pass++) {
            int c = pass * 16 + w;
            float4 v;
            v.x = fmaf(sep[(lane * 4 + 0) * 132 + c], sw, cb);
            v.y = fmaf(sep[(lane * 4 + 1) * 132 + c], sw, cb);
            v.z = fmaf(sep[(lane * 4 + 2) * 132 + c], sw, cb);
            v.w = fmaf(sep[(lane * 4 + 3) * 132 + c], sw, cb);
            *(float4*)&outb[(size_t)(cols0 + c) * S_ + rows0 + lane * 4] = v;
        }
    }
}

// ---------------- launch ----------------
extern "C" void kernel_launch(void* const* d_in, const int* in_sizes, int n_in,
                              void* d_out, int out_size)
{
    const float* hs     = (const float*)d_in[0];
    const float* proj_w = (const float*)d_in[1];
    const float* proj_b = (const float*)d_in[2];
    const float* clf_w  = (const float*)d_in[3];
    const float* clf_b  = (const float*)d_in[4];
    float* out = (float*)d_out;

    unsigned short* w16;
    cudaGetSymbolAddress((void**)&w16, g_w16);

    cudaFuncSetAttribute(proj_gemm_kernel,
                         cudaFuncAttributeMaxDynamicSharedMemorySize, PROJ_SMEM);
    cudaFuncSetAttribute(scores_gemm_kernel,
                         cudaFuncAttributeMaxDynamicSharedMemorySize, SC_SMEM);

    {   // W fp32 -> fp16 only (hs conversion fused into proj)
        convert_w_kernel<<<(P_ * D_ / 4) / 256, 256>>>(proj_w, w16);
    }
    {   // projection + relu -> h fp16: 64x128 tiles, fused hs convert
        dim3 grid(P_ / 128, MROWS / 64);    // (2, 128) = 256 CTAs
        proj_gemm_kernel<<<grid, 256, PROJ_SMEM>>>(hs, proj_b);
    }
    {   // symmetric scores: 128x128 fully-resident tiles, 136/batch
        dim3 grid(136, 1, B_);              // 544 CTAs x 512 threads
        scores_gemm_kernel<<<grid, 512, SC_SMEM>>>(clf_w, clf_b, out);
    }
}

// round 16
// speedup vs baseline: 1.2003x; 1.2003x over previous
#include <cuda_runtime.h>
#include <cuda_fp16.h>
#include <math.h>
#include <cstdint>

// ContactMapHead via single-pass fp16 HMMA GEMMs (tcgen05 rejected by sm_103
// PTX target). fp16 products are exact in the fp32 accumulator.
//   h      = relu(hs @ W^T + b)        hs:[8192,1024] W:[256,1024]
//   scores = (h @ h^T) * s + c         per batch of 4, S=2048
// R15: byte-exact revert to the R8 champion (68.3us measured). The experiment
// matrix (R9-R14: register caps, fused-W, deep A prefetch, zero-barrier
// resident tiles, 128x128 tiles) established R8 as the empirical optimum on
// the mma.sync fallback pipe.

#define B_    4
#define S_    2048
#define D_    1024
#define P_    256
#define MROWS 8192

#define BK    32

// ---- proj smem layout: B 4-stage (ROWB=80) + A 2-slot fp16 staging ----
#define PROJ_ROWB   80
#define PROJ_BSTAGE (128 * PROJ_ROWB)         // 10240
#define PROJ_AOFF   (4 * PROJ_BSTAGE)         // 40960
#define PROJ_ASLOT  (64 * PROJ_ROWB)          // 5120
#define PROJ_SMEM   (PROJ_AOFF + 2 * PROJ_ASLOT)   // 51200

// ---- scores smem layout: BK=64, 2 stages, ROWB=144 ----
#define SC_ROWB    144
#define SC_ASIZE   (64 * SC_ROWB)             // 9216
#define SC_STAGE   ((64 + 128) * SC_ROWB)     // 27648
#define SC_SMEM    (2 * SC_STAGE)             // 55296 (epi 64*132*4=33792 fits)

// ---------------- scratch ----------------
__device__ unsigned short g_w16[(size_t)P_ * D_];
__device__ unsigned short g_h16[(size_t)MROWS * P_];

// ---------------- asm helpers ----------------
__device__ __forceinline__ uint32_t smem_u32(const void* p) {
    uint32_t a;
    asm("{ .reg .u64 t; cvta.to.shared.u64 t, %1; cvt.u32.u64 %0, t; }" : "=r"(a) : "l"(p));
    return a;
}
__device__ __forceinline__ void cpa16(uint32_t s, const void* g) {
    asm volatile("cp.async.cg.shared.global [%0], [%1], 16;" :: "r"(s), "l"(g));
}
#define CP_COMMIT() asm volatile("cp.async.commit_group;" ::: "memory")
#define CP_WAIT2()  asm volatile("cp.async.wait_group 2;" ::: "memory")
#define CP_WAIT1()  asm volatile("cp.async.wait_group 1;" ::: "memory")
#define CP_WAIT0()  asm volatile("cp.async.wait_group 0;" ::: "memory")

#define LDMX4(r, addr) \
    asm volatile("ldmatrix.sync.aligned.m8n8.x4.shared.b16 {%0,%1,%2,%3}, [%4];" \
        : "=r"((r)[0]), "=r"((r)[1]), "=r"((r)[2]), "=r"((r)[3]) : "r"(addr))

#define MMA16816(d, a, b0, b1) \
    asm volatile("mma.sync.aligned.m16n8k16.row.col.f32.f16.f16.f32 " \
        "{%0,%1,%2,%3},{%4,%5,%6,%7},{%8,%9},{%0,%1,%2,%3};" \
        : "+f"((d)[0]), "+f"((d)[1]), "+f"((d)[2]), "+f"((d)[3]) \
        : "r"((a)[0]), "r"((a)[1]), "r"((a)[2]), "r"((a)[3]), "r"(b0), "r"(b1))

#define STS128(addr, v) \
    asm volatile("st.shared.v4.b32 [%0], {%1,%2,%3,%4};" \
        :: "r"(addr), "r"((v).x), "r"((v).y), "r"((v).z), "r"((v).w))

// ---------------- fp32 -> fp16 convert for W only (0.5 MB) ----------------
__global__ __launch_bounds__(256) void convert_w_kernel(
    const float* __restrict__ w, unsigned short* __restrict__ w16)
{
    int i = blockIdx.x * 256 + threadIdx.x;           // (P_*D_)/4 elems
    float4 v = ((const float4*)w)[i];
    __half2 lo = __floats2half2_rn(v.x, v.y);
    __half2 hi = __floats2half2_rn(v.z, v.w);
    uint2 o;
    o.x = *(uint32_t*)&lo;
    o.y = *(uint32_t*)&hi;
    ((uint2*)w16)[i] = o;
}

// ---------------- proj: h = relu(hs@W^T + b) -> h fp16, fused convert -------
// 64x128 tile, 8 warps 2(M)x4(N). A: LDG fp32 -> cvt -> STS (2-slot double
// buffer, register prefetch). B: w16 cp.async 4-stage.
__global__ __launch_bounds__(256) void proj_gemm_kernel(
    const float* __restrict__ hs, const float* __restrict__ bias)
{
    extern __shared__ char smem[];
    uint32_t sbase = smem_u32(smem);
    const int tid = threadIdx.x, lane = tid & 31, w = tid >> 5;
    const int wm = w & 1, wn = w >> 1;
    const int row0 = blockIdx.y * 64, col0 = blockIdx.x * 128;
    const int NC = D_ / BK;   // 32

    // A addressing (per-thread: one 32-elem row segment = 2 float4)
    const float* aptr = hs + (size_t)(row0 + (tid >> 2)) * D_ + (tid & 3) * 8;
    const uint32_t asts = sbase + PROJ_AOFF + (tid >> 2) * PROJ_ROWB + (tid & 3) * 16;

    // prologue: B stages 0..2
#pragma unroll
    for (int i = 0; i < 3; i++) {
        uint32_t sB = sbase + i * PROJ_BSTAGE;
#pragma unroll
        for (int q = 0; q < 2; q++) {
            int ch = tid + q * 256;
            int r = ch >> 2, c16 = ch & 3;
            cpa16(sB + r * PROJ_ROWB + c16 * 16,
                  g_w16 + (size_t)(col0 + r) * D_ + i * BK + c16 * 8);
        }
        CP_COMMIT();
    }
    float4 ax = ((const float4*)aptr)[0];
    float4 ay = ((const float4*)aptr)[1];

    float acc[2][4][4] = {};
    const uint32_t aoffm = (wm * 32 + (lane & 15)) * PROJ_ROWB + (lane >> 4) * 16;
    const uint32_t boff  = (wn * 32 + (lane & 15)) * PROJ_ROWB + (lane >> 4) * 16;

    for (int c = 0; c < NC; c++) {
        float4 nx, ny;
        if (c + 1 < NC) {                      // prefetch next A chunk
            const float4* p = (const float4*)(aptr + (c + 1) * BK);
            nx = p[0]; ny = p[1];
        }
        __syncthreads();                       // prior compute done: A slot free
        {                                      // cvt + STS current A chunk
            __half2 h0 = __floats2half2_rn(ax.x, ax.y);
            __half2 h1 = __floats2half2_rn(ax.z, ax.w);
            __half2 h2 = __floats2half2_rn(ay.x, ay.y);
            __half2 h3 = __floats2half2_rn(ay.z, ay.w);
            uint4 v = { *(uint32_t*)&h0, *(uint32_t*)&h1,
                        *(uint32_t*)&h2, *(uint32_t*)&h3 };
            STS128(asts + (c & 1) * PROJ_ASLOT, v);
        }
        CP_WAIT2();                            // B stage c complete
        __syncthreads();                       // A stores + B visible
        if (c + 3 < NC) {                      // issue B stage c+3
            uint32_t sB = sbase + ((c + 3) & 3) * PROJ_BSTAGE;
#pragma unroll
            for (int q = 0; q < 2; q++) {
                int ch = tid + q * 256;
                int r = ch >> 2, c16 = ch & 3;
                cpa16(sB + r * PROJ_ROWB + c16 * 16,
                      g_w16 + (size_t)(col0 + r) * D_ + (c + 3) * BK + c16 * 8);
            }
        }
        CP_COMMIT();

        uint32_t sA = sbase + PROJ_AOFF + (c & 1) * PROJ_ASLOT;
        uint32_t sB = sbase + (c & 3) * PROJ_BSTAGE;
#pragma unroll
        for (int k16 = 0; k16 < 2; k16++) {
            uint32_t a[2][4], b[2][4];
#pragma unroll
            for (int mt = 0; mt < 2; mt++)
                LDMX4(a[mt], sA + aoffm + mt * 16 * PROJ_ROWB + k16 * 32);
#pragma unroll
            for (int np = 0; np < 2; np++)
                LDMX4(b[np], sB + boff + np * 16 * PROJ_ROWB + k16 * 32);
#pragma unroll
            for (int mt = 0; mt < 2; mt++)
#pragma unroll
                for (int nt = 0; nt < 4; nt++)
                    MMA16816(acc[mt][nt], a[mt], b[nt >> 1][nt & 1], b[nt >> 1][(nt & 1) + 2]);
        }
        ax = nx; ay = ny;
    }

    // epilogue: bias + relu -> h fp16 (direct, coalesced pairs)
    uint32_t* hh = (uint32_t*)g_h16;
#pragma unroll
    for (int nt = 0; nt < 4; nt++) {
        int col = col0 + wn * 32 + nt * 8 + (lane & 3) * 2;
        float b0 = bias[col], b1 = bias[col + 1];
#pragma unroll
        for (int mt = 0; mt < 2; mt++) {
            int r0 = row0 + wm * 32 + mt * 16 + (lane >> 2);
#pragma unroll
            for (int hh2 = 0; hh2 < 2; hh2++) {
                int r = r0 + hh2 * 8;
                float v0 = fmaxf(acc[mt][nt][hh2 * 2 + 0] + b0, 0.f);
                float v1 = fmaxf(acc[mt][nt][hh2 * 2 + 1] + b1, 0.f);
                __half2 p = __floats2half2_rn(v0, v1);
                hh[((size_t)r * P_ + col) >> 1] = *(uint32_t*)&p;
            }
        }
    }
}

// ---------------- scores: 64x128 tiles, BK=64, 2-stage, tri+mirror ----------
// Per batch: col tiles j=0..15 (128 wide), row tiles i=2j..31 (64 tall).
// t = i-2j; t<2 -> inside diagonal 128-block (direct only); t>=2 -> + mirror.
__global__ __launch_bounds__(256) void scores_gemm_kernel(
    const float* __restrict__ clf_w, const float* __restrict__ clf_b,
    float* __restrict__ out)
{
    extern __shared__ char smem[];
    uint32_t sbase = smem_u32(smem);
    const int tid = threadIdx.x, lane = tid & 31, w = tid >> 5;
    const int wm = w & 1, wn = w >> 1;

    int t = blockIdx.x, j = 0;
    while (t >= 32 - 2 * j) { t -= 32 - 2 * j; j++; }
    const int i = 2 * j + t;
    const int rows0 = i * 64, cols0 = j * 128;
    const bool diag = (t < 2);

    const unsigned short* hb = g_h16 + (size_t)blockIdx.z * S_ * P_;
    float* outb = out + (size_t)blockIdx.z * S_ * S_;

    auto load_chunk = [&](int slot, int koff) {
        uint32_t sA = sbase + slot * SC_STAGE;
        uint32_t sB = sA + SC_ASIZE;
#pragma unroll
        for (int q = 0; q < 2; q++) {
            int ch = tid + q * 256;
            int r = ch >> 3, c16 = ch & 7;
            cpa16(sA + r * SC_ROWB + c16 * 16,
                  hb + (size_t)(rows0 + r) * P_ + koff + c16 * 8);
        }
#pragma unroll
        for (int q = 0; q < 4; q++) {
            int ch = tid + q * 256;
            int r = ch >> 3, c16 = ch & 7;
            cpa16(sB + r * SC_ROWB + c16 * 16,
                  hb + (size_t)(cols0 + r) * P_ + koff + c16 * 8);
        }
    };

    load_chunk(0, 0);
    CP_COMMIT();

    float acc[2][4][4] = {};
    const uint32_t aoffm = (wm * 32 + (lane & 15)) * SC_ROWB + (lane >> 4) * 16;
    const uint32_t boff  = (wn * 32 + (lane & 15)) * SC_ROWB + (lane >> 4) * 16;
    const int NC = P_ / 64;   // 4

    for (int c = 0; c < NC; c++) {
        if (c + 1 < NC) {
            load_chunk((c + 1) & 1, (c + 1) * 64);
            CP_COMMIT();
            CP_WAIT1();
        } else {
            CP_WAIT0();
        }
        __syncthreads();

        uint32_t sA = sbase + (c & 1) * SC_STAGE;
        uint32_t sB = sA + SC_ASIZE;
#pragma unroll
        for (int k16 = 0; k16 < 4; k16++) {
            uint32_t a[2][4], b[2][4];
#pragma unroll
            for (int mt = 0; mt < 2; mt++)
                LDMX4(a[mt], sA + aoffm + mt * 16 * SC_ROWB + k16 * 32);
#pragma unroll
            for (int np = 0; np < 2; np++)
                LDMX4(b[np], sB + boff + np * 16 * SC_ROWB + k16 * 32);
#pragma unroll
            for (int mt = 0; mt < 2; mt++)
#pragma unroll
                for (int nt = 0; nt < 4; nt++)
                    MMA16816(acc[mt][nt], a[mt], b[nt >> 1][nt & 1], b[nt >> 1][(nt & 1) + 2]);
        }
        __syncthreads();
    }

    const float sw = clf_w[0], cb = clf_b[0];
    float* sep = (float*)smem;   // [64][132]

#pragma unroll
    for (int mt = 0; mt < 2; mt++)
#pragma unroll
        for (int nt = 0; nt < 4; nt++) {
            int lr = wm * 32 + mt * 16 + (lane >> 2);
            int lc = wn * 32 + nt * 8 + (lane & 3) * 2;
            sep[lr * 132 + lc]           = acc[mt][nt][0];
            sep[lr * 132 + lc + 1]       = acc[mt][nt][1];
            sep[(lr + 8) * 132 + lc]     = acc[mt][nt][2];
            sep[(lr + 8) * 132 + lc + 1] = acc[mt][nt][3];
        }
    __syncthreads();

    // direct block: 64 rows x 128 cols
#pragma unroll
    for (int pass = 0; pass < 8; pass++) {
        int r = pass * 8 + w;
        float4 v = *(const float4*)(sep + r * 132 + lane * 4);
        v.x = fmaf(v.x, sw, cb); v.y = fmaf(v.y, sw, cb);
        v.z = fmaf(v.z, sw, cb); v.w = fmaf(v.w, sw, cb);
        *(float4*)&outb[(size_t)(rows0 + r) * S_ + cols0 + lane * 4] = v;
    }
    // mirrored block: 128 rows x 64 cols
    if (!diag) {
#pragma unroll
        for (int pass = 0; pass < 8; pass++) {
            int c  = pass * 16 + w * 2 + (lane >> 4);
            int rg = lane & 15;
            float4 v;
            v.x = fmaf(sep[(rg * 4 + 0) * 132 + c], sw, cb);
            v.y = fmaf(sep[(rg * 4 + 1) * 132 + c], sw, cb);
            v.z = fmaf(sep[(rg * 4 + 2) * 132 + c], sw, cb);
            v.w = fmaf(sep[(rg * 4 + 3) * 132 + c], sw, cb);
            *(float4*)&outb[(size_t)(cols0 + c) * S_ + rows0 + rg * 4] = v;
        }
    }
}

// ---------------- launch ----------------
extern "C" void kernel_launch(void* const* d_in, const int* in_sizes, int n_in,
                              void* d_out, int out_size)
{
    const float* hs     = (const float*)d_in[0];
    const float* proj_w = (const float*)d_in[1];
    const float* proj_b = (const float*)d_in[2];
    const float* clf_w  = (const float*)d_in[3];
    const float* clf_b  = (const float*)d_in[4];
    float* out = (float*)d_out;

    unsigned short* w16;
    cudaGetSymbolAddress((void**)&w16, g_w16);

    cudaFuncSetAttribute(proj_gemm_kernel,
                         cudaFuncAttributeMaxDynamicSharedMemorySize, PROJ_SMEM);
    cudaFuncSetAttribute(scores_gemm_kernel,
                         cudaFuncAttributeMaxDynamicSharedMemorySize, SC_SMEM);

    {   // W fp32 -> fp16 only (hs conversion fused into proj)
        convert_w_kernel<<<(P_ * D_ / 4) / 256, 256>>>(proj_w, w16);
    }
    {   // projection + relu -> h fp16: 64x128 tiles, fused hs convert
        dim3 grid(P_ / 128, MROWS / 64);    // (2, 128) = 256 CTAs
        proj_gemm_kernel<<<grid, 256, PROJ_SMEM>>>(hs, proj_b);
    }
    {   // symmetric scores: 64x128 tiles, BK=64, 272 tiles/batch
        dim3 grid(272, 1, B_);              // 1088 CTAs
        scores_gemm_kernel<<<grid, 256, SC_SMEM>>>(clf_w, clf_b, out);
    }
}